// round 6
// baseline (speedup 1.0000x reference)
#include <cuda_runtime.h>
#include <cuda_bf16.h>
#include <cstdint>

// ---------------------------------------------------------------------------
// Problem constants
// ---------------------------------------------------------------------------
#define BATCH 128
#define NNODE 4096
#define DIM   32
#define COLS  4096           // BATCH*DIM

// GEMM tiling
#define BM 128               // j tile
#define BN 256               // c tile
#define BK 32                // i chunk (32 bf16 = 64 B per row)
#define STAGES 3
#define A_BYTES (BM * BK * 2)                 // 8 KB
#define B_BYTES (BN * BK * 2)                 // 16 KB
#define STAGE_BYTES (A_BYTES + B_BYTES)       // 24 KB
#define NKITER (NNODE / BK)                   // 128

// Scratch (__device__ globals — allocation-free)
__device__ __nv_bfloat16 g_adjT[(size_t)NNODE * NNODE]; // [j][i]  K-major A
__device__ __nv_bfloat16 g_Tt[(size_t)COLS * NNODE];    // [c][i]  K-major B
__device__ float         g_S[(size_t)NNODE * COLS];     // [j][c]  fp32 self part

// ---------------------------------------------------------------------------
// Helpers (portable ISA only: cp.async / ldmatrix / mma.sync)
// ---------------------------------------------------------------------------
__device__ __forceinline__ uint32_t smem_u32(const void* p) {
    uint32_t a;
    asm("{ .reg .u64 t; cvta.to.shared.u64 t, %1; cvt.u32.u64 %0, t; }"
        : "=r"(a) : "l"(p));
    return a;
}
// 64B logical rows packed 2-per-128B; XOR bits[4:6] with (row>>1)&7.
__device__ __forceinline__ uint32_t swz64(uint32_t off) {
    return off ^ (((off >> 7) & 7) << 4);
}
__device__ __forceinline__ void cp_async16(uint32_t dst, const void* src) {
    asm volatile("cp.async.cg.shared.global [%0], [%1], 16;"
                 :: "r"(dst), "l"(src) : "memory");
}
__device__ __forceinline__ void cp_commit() {
    asm volatile("cp.async.commit_group;" ::: "memory");
}
template <int N>
__device__ __forceinline__ void cp_wait() {
    asm volatile("cp.async.wait_group %0;" :: "n"(N) : "memory");
}
__device__ __forceinline__ void ldsm_x4(uint32_t& r0, uint32_t& r1,
                                        uint32_t& r2, uint32_t& r3, uint32_t a) {
    asm volatile("ldmatrix.sync.aligned.m8n8.x4.shared.b16 {%0,%1,%2,%3}, [%4];"
                 : "=r"(r0), "=r"(r1), "=r"(r2), "=r"(r3) : "r"(a));
}
__device__ __forceinline__ void mma_bf16(float& c0, float& c1, float& c2, float& c3,
                                         uint32_t a0, uint32_t a1, uint32_t a2, uint32_t a3,
                                         uint32_t b0, uint32_t b1) {
    asm volatile(
        "mma.sync.aligned.m16n8k16.row.col.f32.bf16.bf16.f32 "
        "{%0,%1,%2,%3}, {%4,%5,%6,%7}, {%8,%9}, {%0,%1,%2,%3};"
        : "+f"(c0), "+f"(c1), "+f"(c2), "+f"(c3)
        : "r"(a0), "r"(a1), "r"(a2), "r"(a3), "r"(b0), "r"(b1));
}

// ---------------------------------------------------------------------------
// Kernel 1: T^T (bf16, [c][i]) and S (fp32, [j][c]).
// Weights live in registers (lane q owns column q); x broadcast from smem.
// Block = (b, 32-row i-block), 256 threads, lane == q.
// ---------------------------------------------------------------------------
__global__ __launch_bounds__(256) void prep_kernel(
    const float* __restrict__ x,     // [B][N*32]
    const float* __restrict__ Wn,
    const float* __restrict__ Ws)
{
    __shared__ float sx[1024];                 // 32 rows x 32
    __shared__ unsigned short sT[32 * 33];     // [q][il], pitch 33

    int b   = blockIdx.x >> 7;
    int i0  = (blockIdx.x & 127) * 32;
    int tid = threadIdx.x;
    int lane = tid & 31;                       // == q

    // Per-lane weight columns in registers
    float wn[32], ws[32];
#pragma unroll
    for (int p = 0; p < 32; ++p) {
        wn[p] = Wn[p * 32 + lane];
        ws[p] = Ws[p * 32 + lane];
    }

    for (int e = tid; e < 1024; e += 256)
        sx[e] = x[(size_t)b * (NNODE * 32) + (size_t)i0 * 32 + e];
    __syncthreads();

#pragma unroll
    for (int it = 0; it < 4; ++it) {
        int il = (tid >> 5) + it * 8;          // row within block
        float an = 0.f, as = 0.f;
#pragma unroll
        for (int p = 0; p < 32; ++p) {
            float xv = sx[il * 32 + p];        // warp broadcast
            an = fmaf(xv, wn[p], an);
            as = fmaf(xv, ws[p], as);
        }
        g_S[(size_t)(i0 + il) * COLS + b * 32 + lane] = as;
        sT[lane * 33 + il] = __bfloat16_as_ushort(__float2bfloat16(an));
    }
    __syncthreads();

    // Write T^T rows: row c = b*32+q holds 32 bf16 (i0..i0+31) = 16 uint32
    uint32_t* dst = (uint32_t*)g_Tt;
#pragma unroll
    for (int it = 0; it < 2; ++it) {
        int u   = tid + it * 256;              // 0..511
        int row = u >> 4, pr = u & 15;
        uint32_t lo = sT[row * 33 + 2 * pr];
        uint32_t hi = sT[row * 33 + 2 * pr + 1];
        dst[(size_t)(b * 32 + row) * (NNODE / 2) + (i0 >> 1) + pr] = lo | (hi << 16);
    }
}

// ---------------------------------------------------------------------------
// Kernel 2: adjT[j][i] = bf16(adj[i][j]). 64x64 tiles, float4 loads.
// ---------------------------------------------------------------------------
__global__ __launch_bounds__(256) void adjT_kernel(const float* __restrict__ adj)
{
    __shared__ float sA[64][65];
    int j0 = blockIdx.x * 64, i0 = blockIdx.y * 64;
    int tid = threadIdx.x;

#pragma unroll
    for (int it = 0; it < 4; ++it) {
        int e = tid + it * 256;                // 1024 float4 chunks
        int r = e >> 4, c4 = (e & 15) * 4;
        float4 v = *(const float4*)&adj[(size_t)(i0 + r) * NNODE + j0 + c4];
        sA[r][c4 + 0] = v.x; sA[r][c4 + 1] = v.y;
        sA[r][c4 + 2] = v.z; sA[r][c4 + 3] = v.w;
    }
    __syncthreads();

    uint32_t* dst = (uint32_t*)g_adjT;
#pragma unroll
    for (int it = 0; it < 8; ++it) {
        int u = tid + it * 256;                // 2048 uint32
        int row = u >> 5, pr = u & 31;         // row = j-local
        uint32_t lo = __bfloat16_as_ushort(__float2bfloat16(sA[pr * 2][row]));
        uint32_t hi = __bfloat16_as_ushort(__float2bfloat16(sA[pr * 2 + 1][row]));
        dst[(size_t)(j0 + row) * (NNODE / 2) + (i0 >> 1) + pr] = lo | (hi << 16);
    }
}

// ---------------------------------------------------------------------------
// Kernel 3: HMMA GEMM. D[j,c] = sum_i adjT[j,i]*Tt[c,i]; out = relu(D + S)
// BM=128, BN=256, BK=32, 3-stage cp.async, 256 threads (8 warps, 2x4).
// Warp tile 64x64: 4 m-tiles (16) x 8 n-tiles (8).
// ---------------------------------------------------------------------------
__global__ __launch_bounds__(256, 1) void gemm_hmma_kernel(float* __restrict__ out)
{
    extern __shared__ char smem[];
    uint32_t base = (smem_u32(smem) + 1023) & ~1023u;

    int tid = threadIdx.x;
    int wid = tid >> 5, lane = tid & 31;
    int mTile = blockIdx.y * BM;
    int nTile = blockIdx.x * BN;

    int wm = (wid & 1) * 64;     // warp m offset
    int wn = (wid >> 1) * 64;    // warp n offset

    const char* aG = (const char*)g_adjT + (size_t)mTile * (NNODE * 2);
    const char* bG = (const char*)g_Tt   + (size_t)nTile * (NNODE * 2);

    auto load_stage = [&](int kk) {
        int s = kk % STAGES;
        uint32_t aT = base + s * STAGE_BYTES;
        uint32_t bT = aT + A_BYTES;
        const char* ag = aG + (size_t)kk * (BK * 2);
        const char* bg = bG + (size_t)kk * (BK * 2);
#pragma unroll
        for (int it = 0; it < 2; ++it) {       // A: 512 chunks of 16B
            int e = tid + it * 256;
            int r = e >> 2, c = e & 3;
            cp_async16(aT + swz64(r * 64 + c * 16),
                       ag + (size_t)r * (NNODE * 2) + c * 16);
        }
#pragma unroll
        for (int it = 0; it < 4; ++it) {       // B: 1024 chunks of 16B
            int e = tid + it * 256;
            int r = e >> 2, c = e & 3;
            cp_async16(bT + swz64(r * 64 + c * 16),
                       bg + (size_t)r * (NNODE * 2) + c * 16);
        }
        cp_commit();
    };

    // ldmatrix lane offsets (bytes within tile, pre-swizzle)
    int aRow = ((lane >> 3) & 1) * 8 + (lane & 7);
    int aKb  = (lane >> 4) * 16;
    int bRow = (lane >> 4) * 8 + (lane & 7);
    int bKb  = ((lane >> 3) & 1) * 16;

    uint32_t aOff[4], bOff[4];
#pragma unroll
    for (int mi = 0; mi < 4; ++mi)
        aOff[mi] = (uint32_t)(wm + mi * 16 + aRow) * 64 + aKb;
#pragma unroll
    for (int np = 0; np < 4; ++np)
        bOff[np] = (uint32_t)(wn + np * 16 + bRow) * 64 + bKb;

    float acc[4][8][4];
#pragma unroll
    for (int mi = 0; mi < 4; ++mi)
#pragma unroll
        for (int ni = 0; ni < 8; ++ni)
#pragma unroll
            for (int v = 0; v < 4; ++v) acc[mi][ni][v] = 0.f;

    load_stage(0); load_stage(1);

    for (int kk = 0; kk < NKITER; ++kk) {
        cp_wait<STAGES - 2>();
        __syncthreads();

        int s = kk % STAGES;
        uint32_t aT = base + s * STAGE_BYTES;
        uint32_t bT = aT + A_BYTES;

#pragma unroll
        for (int ks = 0; ks < 2; ++ks) {       // two k16 steps per BK=32
            uint32_t a[4][4], b[4][4];
#pragma unroll
            for (int mi = 0; mi < 4; ++mi)
                ldsm_x4(a[mi][0], a[mi][1], a[mi][2], a[mi][3],
                        aT + swz64(aOff[mi] + ks * 32));
#pragma unroll
            for (int np = 0; np < 4; ++np)
                ldsm_x4(b[np][0], b[np][1], b[np][2], b[np][3],
                        bT + swz64(bOff[np] + ks * 32));
#pragma unroll
            for (int mi = 0; mi < 4; ++mi)
#pragma unroll
                for (int ni = 0; ni < 8; ++ni)
                    mma_bf16(acc[mi][ni][0], acc[mi][ni][1],
                             acc[mi][ni][2], acc[mi][ni][3],
                             a[mi][0], a[mi][1], a[mi][2], a[mi][3],
                             b[ni >> 1][(ni & 1) * 2], b[ni >> 1][(ni & 1) * 2 + 1]);
        }
        __syncthreads();
        if (kk + 2 < NKITER) load_stage(kk + 2);
        else cp_commit();                      // keep group count uniform
    }

    // Epilogue: out[b][j][q] = relu(acc + S[j][c])
#pragma unroll
    for (int mi = 0; mi < 4; ++mi) {
        int j0 = mTile + wm + mi * 16 + (lane >> 2);   // rows j0 and j0+8
#pragma unroll
        for (int ni = 0; ni < 8; ++ni) {
            int c = nTile + wn + ni * 8 + (lane & 3) * 2;
            int b = c >> 5, q = c & 31;
            float2 s0 = *(const float2*)(g_S + (size_t)j0 * COLS + c);
            float2 s1 = *(const float2*)(g_S + (size_t)(j0 + 8) * COLS + c);
            float2 o0, o1;
            o0.x = fmaxf(acc[mi][ni][0] + s0.x, 0.f);
            o0.y = fmaxf(acc[mi][ni][1] + s0.y, 0.f);
            o1.x = fmaxf(acc[mi][ni][2] + s1.x, 0.f);
            o1.y = fmaxf(acc[mi][ni][3] + s1.y, 0.f);
            *(float2*)(out + ((size_t)b * NNODE + j0) * DIM + q) = o0;
            *(float2*)(out + ((size_t)b * NNODE + j0 + 8) * DIM + q) = o1;
        }
    }
}

// ---------------------------------------------------------------------------
extern "C" void kernel_launch(void* const* d_in, const int* in_sizes, int n_in,
                              void* d_out, int out_size)
{
    const float* x   = (const float*)d_in[0];
    const float* adj = (const float*)d_in[1];
    const float* Wn  = (const float*)d_in[2];
    const float* Ws  = (const float*)d_in[3];
    float* out = (float*)d_out;

    prep_kernel<<<BATCH * (NNODE / 32), 256>>>(x, Wn, Ws);
    adjT_kernel<<<dim3(NNODE / 64, NNODE / 64), 256>>>(adj);

    int dynSmem = 1024 + STAGES * STAGE_BYTES;   // pad + 3 x 24KB
    cudaFuncSetAttribute(gemm_hmma_kernel,
                         cudaFuncAttributeMaxDynamicSharedMemorySize, dynSmem);
    dim3 grid(COLS / BN, NNODE / BM);
    gemm_hmma_kernel<<<grid, 256, dynSmem>>>(out);
}

// round 8
// speedup vs baseline: 1.4791x; 1.4791x over previous
#include <cuda_runtime.h>
#include <cuda_bf16.h>
#include <cstdint>

// ---------------------------------------------------------------------------
// Problem constants
// ---------------------------------------------------------------------------
#define BATCH 128
#define NNODE 4096
#define DIM   32
#define COLS  4096           // BATCH*DIM

// GEMM tiling (R3-measured best config)
#define BM 128               // j tile
#define BN 128               // c tile
#define BK 32                // i chunk (32 bf16 = 64 B per row)
#define STAGES 4
#define TILE_BYTES (BM * BK * 2)              // 8 KB per operand
#define STAGE_BYTES (2 * TILE_BYTES)          // 16 KB
#define NKITER (NNODE / BK)                   // 128

// Scratch (__device__ globals — allocation-free)
__device__ __nv_bfloat16 g_adjT[(size_t)NNODE * NNODE]; // [j][i]  K-major A
__device__ __nv_bfloat16 g_Tt[(size_t)COLS * NNODE];    // [c][i]  K-major B
__device__ float         g_S[(size_t)NNODE * COLS];     // [j][c]  fp32 self part

// ---------------------------------------------------------------------------
// Helpers (portable ISA only: cp.async / ldmatrix / mma.sync)
// ---------------------------------------------------------------------------
__device__ __forceinline__ uint32_t smem_u32(const void* p) {
    uint32_t a;
    asm("{ .reg .u64 t; cvta.to.shared.u64 t, %1; cvt.u32.u64 %0, t; }"
        : "=r"(a) : "l"(p));
    return a;
}
// 64B logical rows packed 2-per-128B; XOR bits[4:6] with (row>>1)&7.
__device__ __forceinline__ uint32_t swz64(uint32_t off) {
    return off ^ (((off >> 7) & 7) << 4);
}
__device__ __forceinline__ void cp_async16(uint32_t dst, const void* src) {
    asm volatile("cp.async.cg.shared.global [%0], [%1], 16;"
                 :: "r"(dst), "l"(src) : "memory");
}
__device__ __forceinline__ void cp_commit() {
    asm volatile("cp.async.commit_group;" ::: "memory");
}
template <int N>
__device__ __forceinline__ void cp_wait() {
    asm volatile("cp.async.wait_group %0;" :: "n"(N) : "memory");
}
__device__ __forceinline__ void ldsm_x4(uint32_t& r0, uint32_t& r1,
                                        uint32_t& r2, uint32_t& r3, uint32_t a) {
    asm volatile("ldmatrix.sync.aligned.m8n8.x4.shared.b16 {%0,%1,%2,%3}, [%4];"
                 : "=r"(r0), "=r"(r1), "=r"(r2), "=r"(r3) : "r"(a));
}
__device__ __forceinline__ void mma_bf16(float& c0, float& c1, float& c2, float& c3,
                                         uint32_t a0, uint32_t a1, uint32_t a2, uint32_t a3,
                                         uint32_t b0, uint32_t b1) {
    asm volatile(
        "mma.sync.aligned.m16n8k16.row.col.f32.bf16.bf16.f32 "
        "{%0,%1,%2,%3}, {%4,%5,%6,%7}, {%8,%9}, {%0,%1,%2,%3};"
        : "+f"(c0), "+f"(c1), "+f"(c2), "+f"(c3)
        : "r"(a0), "r"(a1), "r"(a2), "r"(a3), "r"(b0), "r"(b1));
}

// ---------------------------------------------------------------------------
// Kernel 1 (v3): T^T (bf16, [c][i]) and S (fp32, [j][c]).
// Weights transposed in smem, pitch 36 -> conflict-free float4 reads.
// 256 threads; warp w, lane q; each thread computes 4 rows (w, w+8, w+16, w+24)
// for its column q. Inner loop: 6x LDS.128 per 32 FMAs.
// ---------------------------------------------------------------------------
__global__ __launch_bounds__(256) void prep_kernel(
    const float* __restrict__ x,     // [B][N*32]
    const float* __restrict__ Wn,
    const float* __restrict__ Ws)
{
    __shared__ float sx[1024];                 // 32 rows x 32 cols
    __shared__ float sWnT[32 * 36];            // [q][p], pitch 36 (16B-aligned rows)
    __shared__ float sWsT[32 * 36];
    __shared__ unsigned short sT[32 * 33];     // [q][il], pitch 33

    int b    = blockIdx.x >> 7;
    int i0   = (blockIdx.x & 127) * 32;
    int tid  = threadIdx.x;
    int lane = tid & 31;                       // == q
    int w    = tid >> 5;                       // warp id 0..7

    // Transposed weight load (one-time, tiny)
    for (int e = tid; e < 1024; e += 256) {
        int p = e >> 5, q = e & 31;
        sWnT[q * 36 + p] = Wn[e];
        sWsT[q * 36 + p] = Ws[e];
    }
    // x tile: 32 rows x 32 floats = 256 float4, fully coalesced
    ((float4*)sx)[tid] =
        ((const float4*)(x + (size_t)b * (NNODE * 32) + (size_t)i0 * 32))[tid];
    __syncthreads();

    float an[4] = {0.f, 0.f, 0.f, 0.f};
    float as_[4] = {0.f, 0.f, 0.f, 0.f};

#pragma unroll
    for (int p4 = 0; p4 < 8; ++p4) {
        float4 wn4 = *(const float4*)&sWnT[lane * 36 + p4 * 4];
        float4 ws4 = *(const float4*)&sWsT[lane * 36 + p4 * 4];
#pragma unroll
        for (int r = 0; r < 4; ++r) {
            float4 xv = *(const float4*)&sx[(w + r * 8) * 32 + p4 * 4]; // broadcast
            an[r]  = fmaf(xv.x, wn4.x, an[r]);
            an[r]  = fmaf(xv.y, wn4.y, an[r]);
            an[r]  = fmaf(xv.z, wn4.z, an[r]);
            an[r]  = fmaf(xv.w, wn4.w, an[r]);
            as_[r] = fmaf(xv.x, ws4.x, as_[r]);
            as_[r] = fmaf(xv.y, ws4.y, as_[r]);
            as_[r] = fmaf(xv.z, ws4.z, as_[r]);
            as_[r] = fmaf(xv.w, ws4.w, as_[r]);
        }
    }

#pragma unroll
    for (int r = 0; r < 4; ++r) {
        int il = w + r * 8;
        g_S[(size_t)(i0 + il) * COLS + b * 32 + lane] = as_[r];   // coalesced
        sT[lane * 33 + il] = __bfloat16_as_ushort(__float2bfloat16(an[r]));
    }
    __syncthreads();

    // Write T^T rows: row c = b*32+q holds 32 bf16 (i0..i0+31) = 16 uint32
    uint32_t* dst = (uint32_t*)g_Tt;
#pragma unroll
    for (int it = 0; it < 2; ++it) {
        int u   = tid + it * 256;              // 0..511
        int row = u >> 4, pr = u & 15;
        uint32_t lo = sT[row * 33 + 2 * pr];
        uint32_t hi = sT[row * 33 + 2 * pr + 1];
        dst[(size_t)(b * 32 + row) * (NNODE / 2) + (i0 >> 1) + pr] = lo | (hi << 16);
    }
}

// ---------------------------------------------------------------------------
// Kernel 2: adjT[j][i] = bf16(adj[i][j]). 64x64 tiles, float4 loads.
// ---------------------------------------------------------------------------
__global__ __launch_bounds__(256) void adjT_kernel(const float* __restrict__ adj)
{
    __shared__ float sA[64][65];
    int j0 = blockIdx.x * 64, i0 = blockIdx.y * 64;
    int tid = threadIdx.x;

#pragma unroll
    for (int it = 0; it < 4; ++it) {
        int e = tid + it * 256;                // 1024 float4 chunks
        int r = e >> 4, c4 = (e & 15) * 4;
        float4 v = *(const float4*)&adj[(size_t)(i0 + r) * NNODE + j0 + c4];
        sA[r][c4 + 0] = v.x; sA[r][c4 + 1] = v.y;
        sA[r][c4 + 2] = v.z; sA[r][c4 + 3] = v.w;
    }
    __syncthreads();

    uint32_t* dst = (uint32_t*)g_adjT;
#pragma unroll
    for (int it = 0; it < 8; ++it) {
        int u = tid + it * 256;                // 2048 uint32
        int row = u >> 5, pr = u & 31;         // row = j-local
        uint32_t lo = __bfloat16_as_ushort(__float2bfloat16(sA[pr * 2][row]));
        uint32_t hi = __bfloat16_as_ushort(__float2bfloat16(sA[pr * 2 + 1][row]));
        dst[(size_t)(j0 + row) * (NNODE / 2) + (i0 >> 1) + pr] = lo | (hi << 16);
    }
}

// ---------------------------------------------------------------------------
// Kernel 3: HMMA GEMM (R3-measured best). D[j,c] = sum_i adjT[j,i]*Tt[c,i];
// out = relu(D + S). BM=128, BN=128, BK=32, 4-stage cp.async, 256 threads.
// Warp tile 64x32: 4 m-tiles (16) x 4 n-tiles (8).
// ---------------------------------------------------------------------------
__global__ __launch_bounds__(256, 2) void gemm_hmma_kernel(float* __restrict__ out)
{
    extern __shared__ char smem[];
    uint32_t base = (smem_u32(smem) + 1023) & ~1023u;

    int tid = threadIdx.x;
    int wid = tid >> 5, lane = tid & 31;
    int mTile = blockIdx.y * BM;
    int nTile = blockIdx.x * BN;

    int wm = (wid & 1) * 64;     // warp m offset
    int wn = (wid >> 1) * 32;    // warp n offset

    const char* aG = (const char*)g_adjT + (size_t)mTile * (NNODE * 2);
    const char* bG = (const char*)g_Tt   + (size_t)nTile * (NNODE * 2);

    auto load_stage = [&](int kk) {
        int s = kk & (STAGES - 1);
        uint32_t aT = base + s * STAGE_BYTES;
        uint32_t bT = aT + TILE_BYTES;
        const char* ag = aG + (size_t)kk * (BK * 2);
        const char* bg = bG + (size_t)kk * (BK * 2);
#pragma unroll
        for (int it = 0; it < 2; ++it) {          // 512 chunks / 256 thr
            int e = tid + it * 256;
            int r = e >> 2, c = e & 3;            // 128 rows x 4 x 16B
            cp_async16(aT + swz64(r * 64 + c * 16),
                       ag + (size_t)r * (NNODE * 2) + c * 16);
            cp_async16(bT + swz64(r * 64 + c * 16),
                       bg + (size_t)r * (NNODE * 2) + c * 16);
        }
        cp_commit();
    };

    // ldmatrix lane offsets (bytes within tile, pre-swizzle)
    int aRow = ((lane >> 3) & 1) * 8 + (lane & 7);
    int aKb  = (lane >> 4) * 16;
    int bRow = (lane >> 4) * 8 + (lane & 7);
    int bKb  = ((lane >> 3) & 1) * 16;

    uint32_t aOff[4], bOff[2];
#pragma unroll
    for (int mi = 0; mi < 4; ++mi)
        aOff[mi] = (uint32_t)(wm + mi * 16 + aRow) * 64 + aKb;
#pragma unroll
    for (int np = 0; np < 2; ++np)
        bOff[np] = (uint32_t)(wn + np * 16 + bRow) * 64 + bKb;

    float acc[4][4][4];
#pragma unroll
    for (int mi = 0; mi < 4; ++mi)
#pragma unroll
        for (int ni = 0; ni < 4; ++ni)
#pragma unroll
            for (int v = 0; v < 4; ++v) acc[mi][ni][v] = 0.f;

    load_stage(0); load_stage(1); load_stage(2);

    for (int kk = 0; kk < NKITER; ++kk) {
        cp_wait<STAGES - 2>();
        __syncthreads();

        int s = kk & (STAGES - 1);
        uint32_t aT = base + s * STAGE_BYTES;
        uint32_t bT = aT + TILE_BYTES;

#pragma unroll
        for (int ks = 0; ks < 2; ++ks) {          // two k16 steps per BK=32
            uint32_t a[4][4], b[2][4];
#pragma unroll
            for (int mi = 0; mi < 4; ++mi)
                ldsm_x4(a[mi][0], a[mi][1], a[mi][2], a[mi][3],
                        aT + swz64(aOff[mi] + ks * 32));
#pragma unroll
            for (int np = 0; np < 2; ++np)
                ldsm_x4(b[np][0], b[np][1], b[np][2], b[np][3],
                        bT + swz64(bOff[np] + ks * 32));
#pragma unroll
            for (int mi = 0; mi < 4; ++mi)
#pragma unroll
                for (int ni = 0; ni < 4; ++ni)
                    mma_bf16(acc[mi][ni][0], acc[mi][ni][1],
                             acc[mi][ni][2], acc[mi][ni][3],
                             a[mi][0], a[mi][1], a[mi][2], a[mi][3],
                             b[ni >> 1][(ni & 1) * 2], b[ni >> 1][(ni & 1) * 2 + 1]);
        }
        __syncthreads();
        if (kk + 3 < NKITER) load_stage(kk + 3);
        else cp_commit();                          // keep group count uniform
    }

    // Epilogue: out[b][j][q] = relu(acc + S[j][c])
#pragma unroll
    for (int mi = 0; mi < 4; ++mi) {
        int j0 = mTile + wm + mi * 16 + (lane >> 2);   // rows j0 and j0+8
#pragma unroll
        for (int ni = 0; ni < 4; ++ni) {
            int c = nTile + wn + ni * 8 + (lane & 3) * 2;
            int b = c >> 5, q = c & 31;
            float2 s0 = *(const float2*)(g_S + (size_t)j0 * COLS + c);
            float2 s1 = *(const float2*)(g_S + (size_t)(j0 + 8) * COLS + c);
            float2 o0, o1;
            o0.x = fmaxf(acc[mi][ni][0] + s0.x, 0.f);
            o0.y = fmaxf(acc[mi][ni][1] + s0.y, 0.f);
            o1.x = fmaxf(acc[mi][ni][2] + s1.x, 0.f);
            o1.y = fmaxf(acc[mi][ni][3] + s1.y, 0.f);
            *(float2*)(out + ((size_t)b * NNODE + j0) * DIM + q) = o0;
            *(float2*)(out + ((size_t)b * NNODE + j0 + 8) * DIM + q) = o1;
        }
    }
}

// ---------------------------------------------------------------------------
extern "C" void kernel_launch(void* const* d_in, const int* in_sizes, int n_in,
                              void* d_out, int out_size)
{
    const float* x   = (const float*)d_in[0];
    const float* adj = (const float*)d_in[1];
    const float* Wn  = (const float*)d_in[2];
    const float* Ws  = (const float*)d_in[3];
    float* out = (float*)d_out;

    prep_kernel<<<BATCH * (NNODE / 32), 256>>>(x, Wn, Ws);
    adjT_kernel<<<dim3(NNODE / 64, NNODE / 64), 256>>>(adj);

    int dynSmem = 1024 + STAGES * STAGE_BYTES;   // pad + 4 x 16KB
    cudaFuncSetAttribute(gemm_hmma_kernel,
                         cudaFuncAttributeMaxDynamicSharedMemorySize, dynSmem);
    dim3 grid(COLS / BN, NNODE / BM);
    gemm_hmma_kernel<<<grid, 256, dynSmem>>>(out);
}

// round 10
// speedup vs baseline: 1.5749x; 1.0648x over previous
#include <cuda_runtime.h>
#include <cuda_bf16.h>
#include <cstdint>

// ---------------------------------------------------------------------------
// Problem constants
// ---------------------------------------------------------------------------
#define BATCH 128
#define NNODE 4096
#define DIM   32
#define COLS  4096           // BATCH*DIM

// GEMM tiling
#define BM 128               // j tile
#define BN 128               // c tile
#define BK 32                // i chunk (32 bf16 = 64 B per row)
#define STAGES 4
#define TILE_BYTES (BM * BK * 2)              // 8 KB per operand
#define STAGE_BYTES (2 * TILE_BYTES)          // 16 KB
#define NKITER (NNODE / BK)                   // 128

// Scratch (__device__ globals — allocation-free)
__device__ __nv_bfloat16 g_adjT[(size_t)NNODE * NNODE]; // [j][i]  K-major A
__device__ __nv_bfloat16 g_Tt[(size_t)COLS * NNODE];    // [c][i]  K-major B
__device__ float         g_S[(size_t)NNODE * COLS];     // [j][c]  fp32 self part

// ---------------------------------------------------------------------------
// Helpers (portable ISA only: cp.async / ldmatrix / mma.sync)
// ---------------------------------------------------------------------------
__device__ __forceinline__ uint32_t smem_u32(const void* p) {
    uint32_t a;
    asm("{ .reg .u64 t; cvta.to.shared.u64 t, %1; cvt.u32.u64 %0, t; }"
        : "=r"(a) : "l"(p));
    return a;
}
// 64B logical rows packed 2-per-128B; XOR bits[4:6] with (row>>1)&7.
__device__ __forceinline__ uint32_t swz64(uint32_t off) {
    return off ^ (((off >> 7) & 7) << 4);
}
__device__ __forceinline__ void cp_async16(uint32_t dst, const void* src) {
    asm volatile("cp.async.cg.shared.global [%0], [%1], 16;"
                 :: "r"(dst), "l"(src) : "memory");
}
__device__ __forceinline__ void cp_commit() {
    asm volatile("cp.async.commit_group;" ::: "memory");
}
template <int N>
__device__ __forceinline__ void cp_wait() {
    asm volatile("cp.async.wait_group %0;" :: "n"(N) : "memory");
}
__device__ __forceinline__ void ldsm_x4(uint32_t& r0, uint32_t& r1,
                                        uint32_t& r2, uint32_t& r3, uint32_t a) {
    asm volatile("ldmatrix.sync.aligned.m8n8.x4.shared.b16 {%0,%1,%2,%3}, [%4];"
                 : "=r"(r0), "=r"(r1), "=r"(r2), "=r"(r3) : "r"(a));
}
__device__ __forceinline__ void mma_bf16(float& c0, float& c1, float& c2, float& c3,
                                         uint32_t a0, uint32_t a1, uint32_t a2, uint32_t a3,
                                         uint32_t b0, uint32_t b1) {
    asm volatile(
        "mma.sync.aligned.m16n8k16.row.col.f32.bf16.bf16.f32 "
        "{%0,%1,%2,%3}, {%4,%5,%6,%7}, {%8,%9}, {%0,%1,%2,%3};"
        : "+f"(c0), "+f"(c1), "+f"(c2), "+f"(c3)
        : "r"(a0), "r"(a1), "r"(a2), "r"(a3), "r"(b0), "r"(b1));
}

// ---------------------------------------------------------------------------
// Kernel 1 (v4): T^T (bf16, [c][i]) and S (fp32, [j][c]).
// 128 rows per block (staging amortized 4x). 256 threads, 8 warps.
// Warp w handles rows w*16..w*16+15 in two groups of 8; lane q = column.
// Per p4 step: 2 weight LDS.128 + 8 x-broadcast LDS.128 -> 16 outputs.
// ---------------------------------------------------------------------------
__global__ __launch_bounds__(256) void prep_kernel(
    const float* __restrict__ x,     // [B][N*32]
    const float* __restrict__ Wn,
    const float* __restrict__ Ws)
{
    __shared__ float sx[128 * 32];             // 16 KB
    __shared__ float sWnT[32 * 36];            // [q][p], pitch 36
    __shared__ float sWsT[32 * 36];
    __shared__ unsigned short sT[32 * 132];    // [q][il 0..127], pitch 132

    int b    = blockIdx.x >> 5;                // batch
    int i0   = (blockIdx.x & 31) * 128;        // row block
    int tid  = threadIdx.x;
    int lane = tid & 31;                       // == q
    int w    = tid >> 5;                       // warp id 0..7

    for (int e = tid; e < 1024; e += 256) {
        int p = e >> 5, q = e & 31;
        sWnT[q * 36 + p] = Wn[e];
        sWsT[q * 36 + p] = Ws[e];
    }
    // x tile: 128 rows x 32 floats = 1024 float4, fully coalesced
    {
        const float4* xg = (const float4*)(x + (size_t)b * (NNODE * 32) + (size_t)i0 * 32);
#pragma unroll
        for (int it = 0; it < 4; ++it)
            ((float4*)sx)[tid + it * 256] = xg[tid + it * 256];
    }
    __syncthreads();

#pragma unroll
    for (int g = 0; g < 2; ++g) {              // two groups of 8 rows
        int rbase = w * 16 + g * 8;
        float an[8], as8[8];
#pragma unroll
        for (int r = 0; r < 8; ++r) { an[r] = 0.f; as8[r] = 0.f; }

#pragma unroll
        for (int p4 = 0; p4 < 8; ++p4) {
            float4 wn4 = *(const float4*)&sWnT[lane * 36 + p4 * 4];
            float4 ws4 = *(const float4*)&sWsT[lane * 36 + p4 * 4];
#pragma unroll
            for (int r = 0; r < 8; ++r) {
                float4 xv = *(const float4*)&sx[(rbase + r) * 32 + p4 * 4]; // bcast
                an[r]  = fmaf(xv.x, wn4.x, an[r]);
                an[r]  = fmaf(xv.y, wn4.y, an[r]);
                an[r]  = fmaf(xv.z, wn4.z, an[r]);
                an[r]  = fmaf(xv.w, wn4.w, an[r]);
                as8[r] = fmaf(xv.x, ws4.x, as8[r]);
                as8[r] = fmaf(xv.y, ws4.y, as8[r]);
                as8[r] = fmaf(xv.z, ws4.z, as8[r]);
                as8[r] = fmaf(xv.w, ws4.w, as8[r]);
            }
        }
#pragma unroll
        for (int r = 0; r < 8; ++r) {
            int il = rbase + r;
            g_S[(size_t)(i0 + il) * COLS + b * 32 + lane] = as8[r];  // coalesced
            sT[lane * 132 + il] = __bfloat16_as_ushort(__float2bfloat16(an[r]));
        }
    }
    __syncthreads();

    // Write T^T rows: row c = b*32+row holds 128 bf16 (i0..i0+127) = 64 uint32
    uint32_t* dst = (uint32_t*)g_Tt;
#pragma unroll
    for (int it = 0; it < 8; ++it) {
        int u   = tid + it * 256;              // 0..2047
        int row = u >> 6, pr = u & 63;
        uint32_t lo = sT[row * 132 + 2 * pr];
        uint32_t hi = sT[row * 132 + 2 * pr + 1];
        dst[(size_t)(b * 32 + row) * (NNODE / 2) + (i0 >> 1) + pr] = lo | (hi << 16);
    }
}

// ---------------------------------------------------------------------------
// Kernel 2: adjT[j][i] = bf16(adj[i][j]). 64x64 tiles, float4 loads.
// ---------------------------------------------------------------------------
__global__ __launch_bounds__(256) void adjT_kernel(const float* __restrict__ adj)
{
    __shared__ float sA[64][65];
    int j0 = blockIdx.x * 64, i0 = blockIdx.y * 64;
    int tid = threadIdx.x;

#pragma unroll
    for (int it = 0; it < 4; ++it) {
        int e = tid + it * 256;                // 1024 float4 chunks
        int r = e >> 4, c4 = (e & 15) * 4;
        float4 v = *(const float4*)&adj[(size_t)(i0 + r) * NNODE + j0 + c4];
        sA[r][c4 + 0] = v.x; sA[r][c4 + 1] = v.y;
        sA[r][c4 + 2] = v.z; sA[r][c4 + 3] = v.w;
    }
    __syncthreads();

    uint32_t* dst = (uint32_t*)g_adjT;
#pragma unroll
    for (int it = 0; it < 8; ++it) {
        int u = tid + it * 256;                // 2048 uint32
        int row = u >> 5, pr = u & 31;         // row = j-local
        uint32_t lo = __bfloat16_as_ushort(__float2bfloat16(sA[pr * 2][row]));
        uint32_t hi = __bfloat16_as_ushort(__float2bfloat16(sA[pr * 2 + 1][row]));
        dst[(size_t)(j0 + row) * (NNODE / 2) + (i0 >> 1) + pr] = lo | (hi << 16);
    }
}

// ---------------------------------------------------------------------------
// Kernel 3: HMMA GEMM. D[j,c] = sum_i adjT[j,i]*Tt[c,i]; out = relu(D + S)
// BM=128, BN=128, BK=32, 4 stages, 128 threads = 4 warps, warp tile 64x64
// (canonical CUTLASS shape). Per ks: 8 ldsm.x4 -> 32 mma (2x better ratio).
// ---------------------------------------------------------------------------
__global__ __launch_bounds__(128, 2) void gemm_hmma_kernel(float* __restrict__ out)
{
    extern __shared__ char smem[];
    uint32_t base = (smem_u32(smem) + 1023) & ~1023u;

    int tid = threadIdx.x;
    int wid = tid >> 5, lane = tid & 31;
    int mTile = blockIdx.y * BM;
    int nTile = blockIdx.x * BN;

    int wm = (wid & 1) * 64;     // warp m offset
    int wn = (wid >> 1) * 64;    // warp n offset

    const char* aG = (const char*)g_adjT + (size_t)mTile * (NNODE * 2);
    const char* bG = (const char*)g_Tt   + (size_t)nTile * (NNODE * 2);

    auto load_stage = [&](int kk) {
        int s = kk & (STAGES - 1);
        uint32_t aT = base + s * STAGE_BYTES;
        uint32_t bT = aT + TILE_BYTES;
        const char* ag = aG + (size_t)kk * (BK * 2);
        const char* bg = bG + (size_t)kk * (BK * 2);
#pragma unroll
        for (int it = 0; it < 4; ++it) {          // 512 chunks / 128 thr
            int e = tid + it * 128;
            int r = e >> 2, c = e & 3;            // 128 rows x 4 x 16B
            cp_async16(aT + swz64(r * 64 + c * 16),
                       ag + (size_t)r * (NNODE * 2) + c * 16);
            cp_async16(bT + swz64(r * 64 + c * 16),
                       bg + (size_t)r * (NNODE * 2) + c * 16);
        }
        cp_commit();
    };

    // ldmatrix lane offsets (bytes within tile, pre-swizzle)
    int aRow = ((lane >> 3) & 1) * 8 + (lane & 7);
    int aKb  = (lane >> 4) * 16;
    int bRow = (lane >> 4) * 8 + (lane & 7);
    int bKb  = ((lane >> 3) & 1) * 16;

    uint32_t aOff[4], bOff[4];
#pragma unroll
    for (int mi = 0; mi < 4; ++mi)
        aOff[mi] = (uint32_t)(wm + mi * 16 + aRow) * 64 + aKb;
#pragma unroll
    for (int np = 0; np < 4; ++np)
        bOff[np] = (uint32_t)(wn + np * 16 + bRow) * 64 + bKb;

    float acc[4][8][4];
#pragma unroll
    for (int mi = 0; mi < 4; ++mi)
#pragma unroll
        for (int ni = 0; ni < 8; ++ni)
#pragma unroll
            for (int v = 0; v < 4; ++v) acc[mi][ni][v] = 0.f;

    load_stage(0); load_stage(1); load_stage(2);

    for (int kk = 0; kk < NKITER; ++kk) {
        cp_wait<STAGES - 2>();
        __syncthreads();

        int s = kk & (STAGES - 1);
        uint32_t aT = base + s * STAGE_BYTES;
        uint32_t bT = aT + TILE_BYTES;

#pragma unroll
        for (int ks = 0; ks < 2; ++ks) {          // two k16 steps per BK=32
            uint32_t a[4][4], b[4][4];
#pragma unroll
            for (int mi = 0; mi < 4; ++mi)
                ldsm_x4(a[mi][0], a[mi][1], a[mi][2], a[mi][3],
                        aT + swz64(aOff[mi] + ks * 32));
#pragma unroll
            for (int np = 0; np < 4; ++np)
                ldsm_x4(b[np][0], b[np][1], b[np][2], b[np][3],
                        bT + swz64(bOff[np] + ks * 32));
#pragma unroll
            for (int mi = 0; mi < 4; ++mi)
#pragma unroll
                for (int ni = 0; ni < 8; ++ni)
                    mma_bf16(acc[mi][ni][0], acc[mi][ni][1],
                             acc[mi][ni][2], acc[mi][ni][3],
                             a[mi][0], a[mi][1], a[mi][2], a[mi][3],
                             b[ni >> 1][(ni & 1) * 2], b[ni >> 1][(ni & 1) * 2 + 1]);
        }
        __syncthreads();
        if (kk + 3 < NKITER) load_stage(kk + 3);
        else cp_commit();                          // keep group count uniform
    }

    // Epilogue: out[b][j][q] = relu(acc + S[j][c])
#pragma unroll
    for (int mi = 0; mi < 4; ++mi) {
        int j0 = mTile + wm + mi * 16 + (lane >> 2);   // rows j0 and j0+8
#pragma unroll
        for (int ni = 0; ni < 8; ++ni) {
            int c = nTile + wn + ni * 8 + (lane & 3) * 2;
            int b = c >> 5, q = c & 31;
            float2 s0 = *(const float2*)(g_S + (size_t)j0 * COLS + c);
            float2 s1 = *(const float2*)(g_S + (size_t)(j0 + 8) * COLS + c);
            float2 o0, o1;
            o0.x = fmaxf(acc[mi][ni][0] + s0.x, 0.f);
            o0.y = fmaxf(acc[mi][ni][1] + s0.y, 0.f);
            o1.x = fmaxf(acc[mi][ni][2] + s1.x, 0.f);
            o1.y = fmaxf(acc[mi][ni][3] + s1.y, 0.f);
            *(float2*)(out + ((size_t)b * NNODE + j0) * DIM + q) = o0;
            *(float2*)(out + ((size_t)b * NNODE + j0 + 8) * DIM + q) = o1;
        }
    }
}

// ---------------------------------------------------------------------------
extern "C" void kernel_launch(void* const* d_in, const int* in_sizes, int n_in,
                              void* d_out, int out_size)
{
    const float* x   = (const float*)d_in[0];
    const float* adj = (const float*)d_in[1];
    const float* Wn  = (const float*)d_in[2];
    const float* Ws  = (const float*)d_in[3];
    float* out = (float*)d_out;

    prep_kernel<<<BATCH * (NNODE / 128), 256>>>(x, Wn, Ws);
    adjT_kernel<<<dim3(NNODE / 64, NNODE / 64), 256>>>(adj);

    int dynSmem = 1024 + STAGES * STAGE_BYTES;   // pad + 4 x 16KB
    cudaFuncSetAttribute(gemm_hmma_kernel,
                         cudaFuncAttributeMaxDynamicSharedMemorySize, dynSmem);
    dim3 grid(COLS / BN, NNODE / BM);
    gemm_hmma_kernel<<<grid, 128, dynSmem>>>(out);
}

// round 12
// speedup vs baseline: 1.5942x; 1.0123x over previous
#include <cuda_runtime.h>
#include <cuda_bf16.h>
#include <cstdint>

// ---------------------------------------------------------------------------
// Problem constants
// ---------------------------------------------------------------------------
#define BATCH 128
#define NNODE 4096
#define DIM   32
#define COLS  4096           // BATCH*DIM

// GEMM tiling
#define BM 128               // j tile
#define BN 128               // c tile
#define BK 32                // i chunk (32 bf16 = 64 B per row)
#define STAGES 4
#define TILE_BYTES (BM * BK * 2)              // 8 KB per operand
#define STAGE_BYTES (2 * TILE_BYTES)          // 16 KB
#define NKITER (NNODE / BK)                   // 128

// Scratch (__device__ globals — allocation-free)
__device__ __nv_bfloat16 g_adjT[(size_t)NNODE * NNODE]; // [j][i]  K-major A
__device__ __nv_bfloat16 g_Tt[(size_t)COLS * NNODE];    // [c][i]  K-major B
__device__ float         g_S[(size_t)NNODE * COLS];     // [j][c]  fp32 self part

// ---------------------------------------------------------------------------
// Helpers (portable ISA only: cp.async / ldmatrix / mma.sync)
// ---------------------------------------------------------------------------
__device__ __forceinline__ uint32_t smem_u32(const void* p) {
    uint32_t a;
    asm("{ .reg .u64 t; cvta.to.shared.u64 t, %1; cvt.u32.u64 %0, t; }"
        : "=r"(a) : "l"(p));
    return a;
}
// 64B logical rows packed 2-per-128B; XOR bits[4:6] with (row>>1)&7.
__device__ __forceinline__ uint32_t swz64(uint32_t off) {
    return off ^ (((off >> 7) & 7) << 4);
}
__device__ __forceinline__ void cp_async16(uint32_t dst, const void* src) {
    asm volatile("cp.async.cg.shared.global [%0], [%1], 16;"
                 :: "r"(dst), "l"(src) : "memory");
}
__device__ __forceinline__ void cp_commit() {
    asm volatile("cp.async.commit_group;" ::: "memory");
}
template <int N>
__device__ __forceinline__ void cp_wait() {
    asm volatile("cp.async.wait_group %0;" :: "n"(N) : "memory");
}
__device__ __forceinline__ void ldsm_x4(uint32_t& r0, uint32_t& r1,
                                        uint32_t& r2, uint32_t& r3, uint32_t a) {
    asm volatile("ldmatrix.sync.aligned.m8n8.x4.shared.b16 {%0,%1,%2,%3}, [%4];"
                 : "=r"(r0), "=r"(r1), "=r"(r2), "=r"(r3) : "r"(a));
}
__device__ __forceinline__ void mma_bf16(float& c0, float& c1, float& c2, float& c3,
                                         uint32_t a0, uint32_t a1, uint32_t a2, uint32_t a3,
                                         uint32_t b0, uint32_t b1) {
    asm volatile(
        "mma.sync.aligned.m16n8k16.row.col.f32.bf16.bf16.f32 "
        "{%0,%1,%2,%3}, {%4,%5,%6,%7}, {%8,%9}, {%0,%1,%2,%3};"
        : "+f"(c0), "+f"(c1), "+f"(c2), "+f"(c3)
        : "r"(a0), "r"(a1), "r"(a2), "r"(a3), "r"(b0), "r"(b1));
}

// ---------------------------------------------------------------------------
// Kernel 1 (v4): T^T (bf16, [c][i]) and S (fp32, [j][c]).
// 128 rows per block. 256 threads; warp w: rows w*16..w*16+15 in 2 groups.
// ---------------------------------------------------------------------------
__global__ __launch_bounds__(256) void prep_kernel(
    const float* __restrict__ x,     // [B][N*32]
    const float* __restrict__ Wn,
    const float* __restrict__ Ws)
{
    __shared__ float sx[128 * 32];             // 16 KB
    __shared__ float sWnT[32 * 36];            // [q][p], pitch 36
    __shared__ float sWsT[32 * 36];
    __shared__ unsigned short sT[32 * 132];    // [q][il 0..127], pitch 132

    int b    = blockIdx.x >> 5;                // batch
    int i0   = (blockIdx.x & 31) * 128;        // row block
    int tid  = threadIdx.x;
    int lane = tid & 31;                       // == q
    int w    = tid >> 5;                       // warp id 0..7

    for (int e = tid; e < 1024; e += 256) {
        int p = e >> 5, q = e & 31;
        sWnT[q * 36 + p] = Wn[e];
        sWsT[q * 36 + p] = Ws[e];
    }
    {
        const float4* xg = (const float4*)(x + (size_t)b * (NNODE * 32) + (size_t)i0 * 32);
#pragma unroll
        for (int it = 0; it < 4; ++it)
            ((float4*)sx)[tid + it * 256] = xg[tid + it * 256];
    }
    __syncthreads();

#pragma unroll
    for (int g = 0; g < 2; ++g) {              // two groups of 8 rows
        int rbase = w * 16 + g * 8;
        float an[8], as8[8];
#pragma unroll
        for (int r = 0; r < 8; ++r) { an[r] = 0.f; as8[r] = 0.f; }

#pragma unroll
        for (int p4 = 0; p4 < 8; ++p4) {
            float4 wn4 = *(const float4*)&sWnT[lane * 36 + p4 * 4];
            float4 ws4 = *(const float4*)&sWsT[lane * 36 + p4 * 4];
#pragma unroll
            for (int r = 0; r < 8; ++r) {
                float4 xv = *(const float4*)&sx[(rbase + r) * 32 + p4 * 4]; // bcast
                an[r]  = fmaf(xv.x, wn4.x, an[r]);
                an[r]  = fmaf(xv.y, wn4.y, an[r]);
                an[r]  = fmaf(xv.z, wn4.z, an[r]);
                an[r]  = fmaf(xv.w, wn4.w, an[r]);
                as8[r] = fmaf(xv.x, ws4.x, as8[r]);
                as8[r] = fmaf(xv.y, ws4.y, as8[r]);
                as8[r] = fmaf(xv.z, ws4.z, as8[r]);
                as8[r] = fmaf(xv.w, ws4.w, as8[r]);
            }
        }
#pragma unroll
        for (int r = 0; r < 8; ++r) {
            int il = rbase + r;
            g_S[(size_t)(i0 + il) * COLS + b * 32 + lane] = as8[r];  // coalesced
            sT[lane * 132 + il] = __bfloat16_as_ushort(__float2bfloat16(an[r]));
        }
    }
    __syncthreads();

    uint32_t* dst = (uint32_t*)g_Tt;
#pragma unroll
    for (int it = 0; it < 8; ++it) {
        int u   = tid + it * 256;              // 0..2047
        int row = u >> 6, pr = u & 63;
        uint32_t lo = sT[row * 132 + 2 * pr];
        uint32_t hi = sT[row * 132 + 2 * pr + 1];
        dst[(size_t)(b * 32 + row) * (NNODE / 2) + (i0 >> 1) + pr] = lo | (hi << 16);
    }
}

// ---------------------------------------------------------------------------
// Kernel 2: adjT[j][i] = bf16(adj[i][j]). 64x64 tiles, float4 loads.
// ---------------------------------------------------------------------------
__global__ __launch_bounds__(256) void adjT_kernel(const float* __restrict__ adj)
{
    __shared__ float sA[64][65];
    int j0 = blockIdx.x * 64, i0 = blockIdx.y * 64;
    int tid = threadIdx.x;

#pragma unroll
    for (int it = 0; it < 4; ++it) {
        int e = tid + it * 256;                // 1024 float4 chunks
        int r = e >> 4, c4 = (e & 15) * 4;
        float4 v = *(const float4*)&adj[(size_t)(i0 + r) * NNODE + j0 + c4];
        sA[r][c4 + 0] = v.x; sA[r][c4 + 1] = v.y;
        sA[r][c4 + 2] = v.z; sA[r][c4 + 3] = v.w;
    }
    __syncthreads();

    uint32_t* dst = (uint32_t*)g_adjT;
#pragma unroll
    for (int it = 0; it < 8; ++it) {
        int u = tid + it * 256;                // 2048 uint32
        int row = u >> 5, pr = u & 31;         // row = j-local
        uint32_t lo = __bfloat16_as_ushort(__float2bfloat16(sA[pr * 2][row]));
        uint32_t hi = __bfloat16_as_ushort(__float2bfloat16(sA[pr * 2 + 1][row]));
        dst[(size_t)(j0 + row) * (NNODE / 2) + (i0 >> 1) + pr] = lo | (hi << 16);
    }
}

// ---------------------------------------------------------------------------
// Kernel 3: HMMA GEMM v2. Single __syncthreads per k-iteration; prefetch
// issued right after the barrier (overlaps cp.async with MMA); loop-invariant
// cp.async addressing hoisted. BM=BN=128, BK=32, 4 stages, 128 thr, 64x64 warp.
// ---------------------------------------------------------------------------
__global__ __launch_bounds__(128, 2) void gemm_hmma_kernel(float* __restrict__ out)
{
    extern __shared__ char smem[];
    uint32_t base = (smem_u32(smem) + 1023) & ~1023u;

    int tid = threadIdx.x;
    int wid = tid >> 5, lane = tid & 31;
    int mTile = blockIdx.y * BM;
    int nTile = blockIdx.x * BN;

    int wm = (wid & 1) * 64;     // warp m offset
    int wn = (wid >> 1) * 64;    // warp n offset

    // Hoisted per-thread cp.async addressing (loop-invariant).
    uint32_t sOff[4];            // swizzled smem offset within a tile
    const char* aSrc[4];         // global srcs at kk=0
    const char* bSrc[4];
    {
        const char* aG = (const char*)g_adjT + (size_t)mTile * (NNODE * 2);
        const char* bG = (const char*)g_Tt   + (size_t)nTile * (NNODE * 2);
#pragma unroll
        for (int it = 0; it < 4; ++it) {
            int e = tid + it * 128;
            int r = e >> 2, c = e & 3;            // 128 rows x 4 x 16B
            sOff[it] = swz64(r * 64 + c * 16);
            aSrc[it] = aG + (size_t)r * (NNODE * 2) + c * 16;
            bSrc[it] = bG + (size_t)r * (NNODE * 2) + c * 16;
        }
    }

    auto load_stage = [&](int kk) {
        uint32_t aT = base + (kk & (STAGES - 1)) * STAGE_BYTES;
        uint32_t bT = aT + TILE_BYTES;
        size_t gAdv = (size_t)kk * (BK * 2);
#pragma unroll
        for (int it = 0; it < 4; ++it) {
            cp_async16(aT + sOff[it], aSrc[it] + gAdv);
            cp_async16(bT + sOff[it], bSrc[it] + gAdv);
        }
        cp_commit();
    };

    // ldmatrix lane offsets (bytes within tile, pre-swizzle)
    int aRow = ((lane >> 3) & 1) * 8 + (lane & 7);
    int aKb  = (lane >> 4) * 16;
    int bRow = (lane >> 4) * 8 + (lane & 7);
    int bKb  = ((lane >> 3) & 1) * 16;

    uint32_t aOff[4], bOff[4];
#pragma unroll
    for (int mi = 0; mi < 4; ++mi)
        aOff[mi] = (uint32_t)(wm + mi * 16 + aRow) * 64 + aKb;
#pragma unroll
    for (int np = 0; np < 4; ++np)
        bOff[np] = (uint32_t)(wn + np * 16 + bRow) * 64 + bKb;

    float acc[4][8][4];
#pragma unroll
    for (int mi = 0; mi < 4; ++mi)
#pragma unroll
        for (int ni = 0; ni < 8; ++ni)
#pragma unroll
            for (int v = 0; v < 4; ++v) acc[mi][ni][v] = 0.f;

    load_stage(0); load_stage(1); load_stage(2);

    for (int kk = 0; kk < NKITER; ++kk) {
        cp_wait<STAGES - 2>();
        __syncthreads();          // single barrier per iteration

        // Prefetch kk+3 -> stage (kk-1)&3; its readers passed the barrier above.
        if (kk + 3 < NKITER) load_stage(kk + 3);
        else cp_commit();         // keep group count uniform for cp_wait math

        uint32_t aT = base + (kk & (STAGES - 1)) * STAGE_BYTES;
        uint32_t bT = aT + TILE_BYTES;

#pragma unroll
        for (int ks = 0; ks < 2; ++ks) {          // two k16 steps per BK=32
            uint32_t a[4][4], b[4][4];
#pragma unroll
            for (int mi = 0; mi < 4; ++mi)
                ldsm_x4(a[mi][0], a[mi][1], a[mi][2], a[mi][3],
                        aT + swz64(aOff[mi] + ks * 32));
#pragma unroll
            for (int np = 0; np < 4; ++np)
                ldsm_x4(b[np][0], b[np][1], b[np][2], b[np][3],
                        bT + swz64(bOff[np] + ks * 32));
#pragma unroll
            for (int mi = 0; mi < 4; ++mi)
#pragma unroll
                for (int ni = 0; ni < 8; ++ni)
                    mma_bf16(acc[mi][ni][0], acc[mi][ni][1],
                             acc[mi][ni][2], acc[mi][ni][3],
                             a[mi][0], a[mi][1], a[mi][2], a[mi][3],
                             b[ni >> 1][(ni & 1) * 2], b[ni >> 1][(ni & 1) * 2 + 1]);
        }
        // no trailing barrier: next iteration's top barrier orders reads/writes
    }

    // Epilogue: out[b][j][q] = relu(acc + S[j][c])
#pragma unroll
    for (int mi = 0; mi < 4; ++mi) {
        int j0 = mTile + wm + mi * 16 + (lane >> 2);   // rows j0 and j0+8
#pragma unroll
        for (int ni = 0; ni < 8; ++ni) {
            int c = nTile + wn + ni * 8 + (lane & 3) * 2;
            int b = c >> 5, q = c & 31;
            float2 s0 = *(const float2*)(g_S + (size_t)j0 * COLS + c);
            float2 s1 = *(const float2*)(g_S + (size_t)(j0 + 8) * COLS + c);
            float2 o0, o1;
            o0.x = fmaxf(acc[mi][ni][0] + s0.x, 0.f);
            o0.y = fmaxf(acc[mi][ni][1] + s0.y, 0.f);
            o1.x = fmaxf(acc[mi][ni][2] + s1.x, 0.f);
            o1.y = fmaxf(acc[mi][ni][3] + s1.y, 0.f);
            *(float2*)(out + ((size_t)b * NNODE + j0) * DIM + q) = o0;
            *(float2*)(out + ((size_t)b * NNODE + j0 + 8) * DIM + q) = o1;
        }
    }
}

// ---------------------------------------------------------------------------
extern "C" void kernel_launch(void* const* d_in, const int* in_sizes, int n_in,
                              void* d_out, int out_size)
{
    const float* x   = (const float*)d_in[0];
    const float* adj = (const float*)d_in[1];
    const float* Wn  = (const float*)d_in[2];
    const float* Ws  = (const float*)d_in[3];
    float* out = (float*)d_out;

    prep_kernel<<<BATCH * (NNODE / 128), 256>>>(x, Wn, Ws);
    adjT_kernel<<<dim3(NNODE / 64, NNODE / 64), 256>>>(adj);

    int dynSmem = 1024 + STAGES * STAGE_BYTES;   // pad + 4 x 16KB
    cudaFuncSetAttribute(gemm_hmma_kernel,
                         cudaFuncAttributeMaxDynamicSharedMemorySize, dynSmem);
    dim3 grid(COLS / BN, NNODE / BM);
    gemm_hmma_kernel<<<grid, 128, dynSmem>>>(out);
}

// round 14
// speedup vs baseline: 1.6228x; 1.0179x over previous
#include <cuda_runtime.h>
#include <cuda_bf16.h>
#include <cstdint>

// ---------------------------------------------------------------------------
// Problem constants
// ---------------------------------------------------------------------------
#define BATCH 128
#define NNODE 4096
#define DIM   32
#define COLS  4096           // BATCH*DIM

// GEMM tiling
#define BM 128               // j tile
#define BN 128               // c tile
#define BK 32                // i chunk (32 bf16 = 64 B per row)
#define STAGES 4
#define TILE_BYTES (BM * BK * 2)              // 8 KB per operand
#define STAGE_BYTES (2 * TILE_BYTES)          // 16 KB
#define NKITER (NNODE / BK)                   // 128

// Scratch (__device__ globals — allocation-free)
__device__ __nv_bfloat16 g_adjT[(size_t)NNODE * NNODE]; // [j][i]  K-major A
__device__ __nv_bfloat16 g_Tt[(size_t)COLS * NNODE];    // [c][i]  K-major B
__device__ float         g_S[(size_t)NNODE * COLS];     // [j][c]  fp32 self part

// ---------------------------------------------------------------------------
// Helpers (portable ISA only: cp.async / ldmatrix / mma.sync)
// ---------------------------------------------------------------------------
__device__ __forceinline__ uint32_t smem_u32(const void* p) {
    uint32_t a;
    asm("{ .reg .u64 t; cvta.to.shared.u64 t, %1; cvt.u32.u64 %0, t; }"
        : "=r"(a) : "l"(p));
    return a;
}
// 64B logical rows packed 2-per-128B; XOR bits[4:6] with (row>>1)&7.
__device__ __forceinline__ uint32_t swz64(uint32_t off) {
    return off ^ (((off >> 7) & 7) << 4);
}
__device__ __forceinline__ void cp_async16(uint32_t dst, const void* src) {
    asm volatile("cp.async.cg.shared.global [%0], [%1], 16;"
                 :: "r"(dst), "l"(src) : "memory");
}
__device__ __forceinline__ void cp_commit() {
    asm volatile("cp.async.commit_group;" ::: "memory");
}
template <int N>
__device__ __forceinline__ void cp_wait() {
    asm volatile("cp.async.wait_group %0;" :: "n"(N) : "memory");
}
__device__ __forceinline__ void ldsm_x4(uint32_t& r0, uint32_t& r1,
                                        uint32_t& r2, uint32_t& r3, uint32_t a) {
    asm volatile("ldmatrix.sync.aligned.m8n8.x4.shared.b16 {%0,%1,%2,%3}, [%4];"
                 : "=r"(r0), "=r"(r1), "=r"(r2), "=r"(r3) : "r"(a));
}
__device__ __forceinline__ void mma_bf16(float& c0, float& c1, float& c2, float& c3,
                                         uint32_t a0, uint32_t a1, uint32_t a2, uint32_t a3,
                                         uint32_t b0, uint32_t b1) {
    asm volatile(
        "mma.sync.aligned.m16n8k16.row.col.f32.bf16.bf16.f32 "
        "{%0,%1,%2,%3}, {%4,%5,%6,%7}, {%8,%9}, {%0,%1,%2,%3};"
        : "+f"(c0), "+f"(c1), "+f"(c2), "+f"(c3)
        : "r"(a0), "r"(a1), "r"(a2), "r"(a3), "r"(b0), "r"(b1));
}

// ---------------------------------------------------------------------------
// Kernel 1 (v5): T^T (bf16, [c][i]) and S (fp32, [j][c]).
// 128 rows/block, 256 threads. 4-row groups x 4 -> 8 live accumulators,
// ~70 regs, 3 CTAs/SM target (occupancy over raw LDS count).
// ---------------------------------------------------------------------------
__global__ __launch_bounds__(256) void prep_kernel(
    const float* __restrict__ x,     // [B][N*32]
    const float* __restrict__ Wn,
    const float* __restrict__ Ws)
{
    __shared__ float sx[128 * 32];             // 16 KB
    __shared__ float sWnT[32 * 36];            // [q][p], pitch 36
    __shared__ float sWsT[32 * 36];
    __shared__ unsigned short sT[32 * 132];    // [q][il 0..127], pitch 132

    int b    = blockIdx.x >> 5;                // batch
    int i0   = (blockIdx.x & 31) * 128;        // row block
    int tid  = threadIdx.x;
    int lane = tid & 31;                       // == q
    int w    = tid >> 5;                       // warp id 0..7

    for (int e = tid; e < 1024; e += 256) {
        int p = e >> 5, q = e & 31;
        sWnT[q * 36 + p] = Wn[e];
        sWsT[q * 36 + p] = Ws[e];
    }
    {
        const float4* xg = (const float4*)(x + (size_t)b * (NNODE * 32) + (size_t)i0 * 32);
#pragma unroll
        for (int it = 0; it < 4; ++it)
            ((float4*)sx)[tid + it * 256] = xg[tid + it * 256];
    }
    __syncthreads();

#pragma unroll
    for (int g = 0; g < 4; ++g) {              // four groups of 4 rows
        int rbase = w * 16 + g * 4;
        float an[4], as4[4];
#pragma unroll
        for (int r = 0; r < 4; ++r) { an[r] = 0.f; as4[r] = 0.f; }

#pragma unroll
        for (int p4 = 0; p4 < 8; ++p4) {
            float4 wn4 = *(const float4*)&sWnT[lane * 36 + p4 * 4];
            float4 ws4 = *(const float4*)&sWsT[lane * 36 + p4 * 4];
#pragma unroll
            for (int r = 0; r < 4; ++r) {
                float4 xv = *(const float4*)&sx[(rbase + r) * 32 + p4 * 4]; // bcast
                an[r]  = fmaf(xv.x, wn4.x, an[r]);
                an[r]  = fmaf(xv.y, wn4.y, an[r]);
                an[r]  = fmaf(xv.z, wn4.z, an[r]);
                an[r]  = fmaf(xv.w, wn4.w, an[r]);
                as4[r] = fmaf(xv.x, ws4.x, as4[r]);
                as4[r] = fmaf(xv.y, ws4.y, as4[r]);
                as4[r] = fmaf(xv.z, ws4.z, as4[r]);
                as4[r] = fmaf(xv.w, ws4.w, as4[r]);
            }
        }
#pragma unroll
        for (int r = 0; r < 4; ++r) {
            int il = rbase + r;
            g_S[(size_t)(i0 + il) * COLS + b * 32 + lane] = as4[r];  // coalesced
            sT[lane * 132 + il] = __bfloat16_as_ushort(__float2bfloat16(an[r]));
        }
    }
    __syncthreads();

    uint32_t* dst = (uint32_t*)g_Tt;
#pragma unroll
    for (int it = 0; it < 8; ++it) {
        int u   = tid + it * 256;              // 0..2047
        int row = u >> 6, pr = u & 63;
        uint32_t lo = sT[row * 132 + 2 * pr];
        uint32_t hi = sT[row * 132 + 2 * pr + 1];
        dst[(size_t)(b * 32 + row) * (NNODE / 2) + (i0 >> 1) + pr] = lo | (hi << 16);
    }
}

// ---------------------------------------------------------------------------
// Kernel 2: adjT[j][i] = bf16(adj[i][j]). 64x64 tiles, float4 loads.
// ---------------------------------------------------------------------------
__global__ __launch_bounds__(256) void adjT_kernel(const float* __restrict__ adj)
{
    __shared__ float sA[64][65];
    int j0 = blockIdx.x * 64, i0 = blockIdx.y * 64;
    int tid = threadIdx.x;

#pragma unroll
    for (int it = 0; it < 4; ++it) {
        int e = tid + it * 256;                // 1024 float4 chunks
        int r = e >> 4, c4 = (e & 15) * 4;
        float4 v = *(const float4*)&adj[(size_t)(i0 + r) * NNODE + j0 + c4];
        sA[r][c4 + 0] = v.x; sA[r][c4 + 1] = v.y;
        sA[r][c4 + 2] = v.z; sA[r][c4 + 3] = v.w;
    }
    __syncthreads();

    uint32_t* dst = (uint32_t*)g_adjT;
#pragma unroll
    for (int it = 0; it < 8; ++it) {
        int u = tid + it * 256;                // 2048 uint32
        int row = u >> 5, pr = u & 31;         // row = j-local
        uint32_t lo = __bfloat16_as_ushort(__float2bfloat16(sA[pr * 2][row]));
        uint32_t hi = __bfloat16_as_ushort(__float2bfloat16(sA[pr * 2 + 1][row]));
        dst[(size_t)(j0 + row) * (NNODE / 2) + (i0 >> 1) + pr] = lo | (hi << 16);
    }
}

// ---------------------------------------------------------------------------
// Kernel 3: HMMA GEMM v3. Register fragment double-buffering: ldsm for ks=1
// issued before the ks=0 MMA burst so LDS latency overlaps tensor issue.
// BM=BN=128, BK=32, 4 stages, 128 thr (4 warps), warp tile 64x64.
// ---------------------------------------------------------------------------
__global__ __launch_bounds__(128, 2) void gemm_hmma_kernel(float* __restrict__ out)
{
    extern __shared__ char smem[];
    uint32_t base = (smem_u32(smem) + 1023) & ~1023u;

    int tid = threadIdx.x;
    int wid = tid >> 5, lane = tid & 31;
    int mTile = blockIdx.y * BM;
    int nTile = blockIdx.x * BN;

    int wm = (wid & 1) * 64;     // warp m offset
    int wn = (wid >> 1) * 64;    // warp n offset

    // Hoisted per-thread cp.async addressing (loop-invariant).
    uint32_t sOff[4];
    const char* aSrc[4];
    const char* bSrc[4];
    {
        const char* aG = (const char*)g_adjT + (size_t)mTile * (NNODE * 2);
        const char* bG = (const char*)g_Tt   + (size_t)nTile * (NNODE * 2);
#pragma unroll
        for (int it = 0; it < 4; ++it) {
            int e = tid + it * 128;
            int r = e >> 2, c = e & 3;            // 128 rows x 4 x 16B
            sOff[it] = swz64(r * 64 + c * 16);
            aSrc[it] = aG + (size_t)r * (NNODE * 2) + c * 16;
            bSrc[it] = bG + (size_t)r * (NNODE * 2) + c * 16;
        }
    }

    auto load_stage = [&](int kk) {
        uint32_t aT = base + (kk & (STAGES - 1)) * STAGE_BYTES;
        uint32_t bT = aT + TILE_BYTES;
        size_t gAdv = (size_t)kk * (BK * 2);
#pragma unroll
        for (int it = 0; it < 4; ++it) {
            cp_async16(aT + sOff[it], aSrc[it] + gAdv);
            cp_async16(bT + sOff[it], bSrc[it] + gAdv);
        }
        cp_commit();
    };

    // ldmatrix lane offsets (bytes within tile, pre-swizzle)
    int aRow = ((lane >> 3) & 1) * 8 + (lane & 7);
    int aKb  = (lane >> 4) * 16;
    int bRow = (lane >> 4) * 8 + (lane & 7);
    int bKb  = ((lane >> 3) & 1) * 16;

    uint32_t aOff[4], bOff[4];
#pragma unroll
    for (int mi = 0; mi < 4; ++mi)
        aOff[mi] = (uint32_t)(wm + mi * 16 + aRow) * 64 + aKb;
#pragma unroll
    for (int np = 0; np < 4; ++np)
        bOff[np] = (uint32_t)(wn + np * 16 + bRow) * 64 + bKb;

    float acc[4][8][4];
#pragma unroll
    for (int mi = 0; mi < 4; ++mi)
#pragma unroll
        for (int ni = 0; ni < 8; ++ni)
#pragma unroll
            for (int v = 0; v < 4; ++v) acc[mi][ni][v] = 0.f;

    load_stage(0); load_stage(1); load_stage(2);

    for (int kk = 0; kk < NKITER; ++kk) {
        cp_wait<STAGES - 2>();
        __syncthreads();          // single barrier per iteration

        uint32_t aT = base + (kk & (STAGES - 1)) * STAGE_BYTES;
        uint32_t bT = aT + TILE_BYTES;

        uint32_t a0[4][4], b0[4][4], a1[4][4], b1[4][4];

        // fragments for ks=0
#pragma unroll
        for (int mi = 0; mi < 4; ++mi)
            ldsm_x4(a0[mi][0], a0[mi][1], a0[mi][2], a0[mi][3],
                    aT + swz64(aOff[mi]));
#pragma unroll
        for (int np = 0; np < 4; ++np)
            ldsm_x4(b0[np][0], b0[np][1], b0[np][2], b0[np][3],
                    bT + swz64(bOff[np]));

        // prefetch kk+3 -> stage (kk-1)&3; readers passed the barrier above
        if (kk + 3 < NKITER) load_stage(kk + 3);
        else cp_commit();

        // fragments for ks=1 — overlap their latency with the ks=0 MMA burst
#pragma unroll
        for (int mi = 0; mi < 4; ++mi)
            ldsm_x4(a1[mi][0], a1[mi][1], a1[mi][2], a1[mi][3],
                    aT + swz64(aOff[mi] + 32));
#pragma unroll
        for (int np = 0; np < 4; ++np)
            ldsm_x4(b1[np][0], b1[np][1], b1[np][2], b1[np][3],
                    bT + swz64(bOff[np] + 32));

#pragma unroll
        for (int mi = 0; mi < 4; ++mi)
#pragma unroll
            for (int ni = 0; ni < 8; ++ni)
                mma_bf16(acc[mi][ni][0], acc[mi][ni][1],
                         acc[mi][ni][2], acc[mi][ni][3],
                         a0[mi][0], a0[mi][1], a0[mi][2], a0[mi][3],
                         b0[ni >> 1][(ni & 1) * 2], b0[ni >> 1][(ni & 1) * 2 + 1]);
#pragma unroll
        for (int mi = 0; mi < 4; ++mi)
#pragma unroll
            for (int ni = 0; ni < 8; ++ni)
                mma_bf16(acc[mi][ni][0], acc[mi][ni][1],
                         acc[mi][ni][2], acc[mi][ni][3],
                         a1[mi][0], a1[mi][1], a1[mi][2], a1[mi][3],
                         b1[ni >> 1][(ni & 1) * 2], b1[ni >> 1][(ni & 1) * 2 + 1]);
        // no trailing barrier: next iteration's top barrier orders reuse
    }

    // Epilogue: out[b][j][q] = relu(acc + S[j][c])
#pragma unroll
    for (int mi = 0; mi < 4; ++mi) {
        int j0 = mTile + wm + mi * 16 + (lane >> 2);   // rows j0 and j0+8
#pragma unroll
        for (int ni = 0; ni < 8; ++ni) {
            int c = nTile + wn + ni * 8 + (lane & 3) * 2;
            int b = c >> 5, q = c & 31;
            float2 s0 = *(const float2*)(g_S + (size_t)j0 * COLS + c);
            float2 s1 = *(const float2*)(g_S + (size_t)(j0 + 8) * COLS + c);
            float2 o0, o1;
            o0.x = fmaxf(acc[mi][ni][0] + s0.x, 0.f);
            o0.y = fmaxf(acc[mi][ni][1] + s0.y, 0.f);
            o1.x = fmaxf(acc[mi][ni][2] + s1.x, 0.f);
            o1.y = fmaxf(acc[mi][ni][3] + s1.y, 0.f);
            *(float2*)(out + ((size_t)b * NNODE + j0) * DIM + q) = o0;
            *(float2*)(out + ((size_t)b * NNODE + j0 + 8) * DIM + q) = o1;
        }
    }
}

// ---------------------------------------------------------------------------
extern "C" void kernel_launch(void* const* d_in, const int* in_sizes, int n_in,
                              void* d_out, int out_size)
{
    const float* x   = (const float*)d_in[0];
    const float* adj = (const float*)d_in[1];
    const float* Wn  = (const float*)d_in[2];
    const float* Ws  = (const float*)d_in[3];
    float* out = (float*)d_out;

    prep_kernel<<<BATCH * (NNODE / 128), 256>>>(x, Wn, Ws);
    adjT_kernel<<<dim3(NNODE / 64, NNODE / 64), 256>>>(adj);

    int dynSmem = 1024 + STAGES * STAGE_BYTES;   // pad + 4 x 16KB
    cudaFuncSetAttribute(gemm_hmma_kernel,
                         cudaFuncAttributeMaxDynamicSharedMemorySize, dynSmem);
    dim3 grid(COLS / BN, NNODE / BM);
    gemm_hmma_kernel<<<grid, 128, dynSmem>>>(out);
}